// round 17
// baseline (speedup 1.0000x reference)
#include <cuda_runtime.h>
#include <math.h>

// Chamfer, N=M=16384, D=3 — EXACT grid NN. 32^3 cells over [-4.8,4.8]^3, s=0.3.
// Fast path: hardcoded 27-cell (9-row) probe, unrolled, MLP-batched loads.
// Rare tail (~3%): generic ring r>=2 with bound (r*s)^2. Exact by construction.
// 4 kernels [hist, scan, scatter, query+reduce]; query = ncu launch #4.
// g_cnt zero-init; scatter's atomicSub restores zeros => graph-replay idempotent.

#define G     32
#define NC    (G*G*G)
#define BOUND 4.8f
#define CS    (2.0f*BOUND/(float)G)   // 0.3
#define MAXN  16384
#define HTPB  256
#define QTPB  256
#define QWPB  (QTPB/32)
#define MAXQ  (2*MAXN)
#define QGRID (MAXQ/QWPB)             // 4096
#define STPB  1024
#define CPS   (NC/STPB)

__device__ unsigned g_cnt[2][NC];
__device__ unsigned g_off[2][NC+1];
__device__ float4   g_pts[2][MAXN];
__device__ float    g_bsum[QGRID];
__device__ unsigned g_ctr = 0;

__device__ __forceinline__ int cellco(float x) {
    int c = __float2int_rd((x + BOUND) * (1.0f/CS));
    return min(max(c, 0), G-1);
}

__global__ void hist_kernel(const float* __restrict__ p1, int n1,
                            const float* __restrict__ p2, int n2) {
    int i = blockIdx.x * blockDim.x + threadIdx.x;
    if (i >= n1 + n2) return;
    const float* p; int s, idx;
    if (i < n1) { p = p1; s = 0; idx = i; } else { p = p2; s = 1; idx = i - n1; }
    float x = p[3*idx], y = p[3*idx+1], z = p[3*idx+2];
    int c = (cellco(z)*G + cellco(y))*G + cellco(x);
    atomicAdd(&g_cnt[s][c], 1u);
}

__global__ void __launch_bounds__(STPB) scan_kernel() {
    const int s = blockIdx.x;
    const int tid = threadIdx.x, lane = tid & 31, wid = tid >> 5;
    __shared__ unsigned wsum[32];
    unsigned tsum = 0;
    #pragma unroll
    for (int k = 0; k < CPS; k++) tsum += g_cnt[s][tid*CPS + k];
    unsigned v = tsum;
    #pragma unroll
    for (int o = 1; o < 32; o <<= 1) {
        unsigned t = __shfl_up_sync(0xffffffffu, v, o);
        if (lane >= o) v += t;
    }
    if (lane == 31) wsum[wid] = v;
    __syncthreads();
    if (wid == 0) {
        unsigned w = wsum[lane];
        #pragma unroll
        for (int o = 1; o < 32; o <<= 1) {
            unsigned t = __shfl_up_sync(0xffffffffu, w, o);
            if (lane >= o) w += t;
        }
        wsum[lane] = w;
    }
    __syncthreads();
    unsigned run = v - tsum + (wid > 0 ? wsum[wid-1] : 0u);
    #pragma unroll
    for (int k = 0; k < CPS; k++) {
        unsigned c = g_cnt[s][tid*CPS + k];
        g_off[s][tid*CPS + k] = run;
        run += c;
    }
    if (tid == STPB-1) g_off[s][NC] = run;
}

__global__ void scatter_kernel(const float* __restrict__ p1, int n1,
                               const float* __restrict__ p2, int n2) {
    int i = blockIdx.x * blockDim.x + threadIdx.x;
    if (i >= n1 + n2) return;
    const float* p; int s, idx;
    if (i < n1) { p = p1; s = 0; idx = i; } else { p = p2; s = 1; idx = i - n1; }
    float x = p[3*idx], y = p[3*idx+1], z = p[3*idx+2];
    int c = (cellco(z)*G + cellco(y))*G + cellco(x);
    unsigned t = atomicSub(&g_cnt[s][c], 1u);   // restores 0 for next replay
    g_pts[s][g_off[s][c] + t - 1u] = make_float4(x, y, z, 0.0f);
}

__global__ void __launch_bounds__(QTPB)
query_kernel(const float* __restrict__ p1, int n1,
             const float* __restrict__ p2, int n2,
             float* __restrict__ out) {
    __shared__ float swsum[QWPB];
    const int lane = threadIdx.x & 31, wid = threadIdx.x >> 5;
    const int gw = blockIdx.x * QWPB + wid;
    const int total = n1 + n2;
    const float INF = __uint_as_float(0x7F800000u);
    float res = 0.0f;

    if (gw < total) {
        const float* q; int s, idx;
        if (gw < n1) { q = p1; s = 1; idx = gw; }
        else         { q = p2; s = 0; idx = gw - n1; }
        const float qx = q[3*idx], qy = q[3*idx+1], qz = q[3*idx+2];
        const int cx = cellco(qx), cy = cellco(qy), cz = cellco(qz);
        const unsigned* __restrict__ off = g_off[s];
        const float4*   __restrict__ pts = g_pts[s];

        // ---- fast path: fixed 27-cell box, 9 rows, lane 'rid' holds row rid ----
        const int xlo = max(cx-1, 0), xhi = min(cx+1, G-1);
        unsigned lo = 0, hi = 0;
        if (lane < 9) {
            int zi = min(max(cz + (lane/3) - 1, 0), G-1);
            int yi = min(max(cy + (lane%3) - 1, 0), G-1);
            int rowb = (zi*G + yi)*G;
            lo = off[rowb + xlo];
            hi = off[rowb + xhi + 1];
        }
        float best = INF;
        #pragma unroll
        for (int rid = 0; rid < 9; rid++) {
            unsigned rlo = __shfl_sync(0xffffffffu, lo, rid);
            unsigned rhi = __shfl_sync(0xffffffffu, hi, rid);
            for (unsigned k = rlo + lane; k < rhi; k += 32) {
                float4 pt = pts[k];
                float dx = pt.x - qx, dy = pt.y - qy, dz = pt.z - qz;
                best = fminf(best, fmaf(dx, dx, fmaf(dy, dy, dz*dz)));
            }
        }
        float b = best;
        b = fminf(b, __shfl_xor_sync(0xffffffffu, b, 16));
        b = fminf(b, __shfl_xor_sync(0xffffffffu, b, 8));
        b = fminf(b, __shfl_xor_sync(0xffffffffu, b, 4));
        b = fminf(b, __shfl_xor_sync(0xffffffffu, b, 2));
        b = fminf(b, __shfl_xor_sync(0xffffffffu, b, 1));

        // ---- rare tail: generic rings r>=2 until bound proves optimality ----
        if (CS*CS < b) {
            best = b;
            for (int r = 2; r < G; r++) {
                const int zlo = max(cz-r, 0), zhi = min(cz+r, G-1);
                const int ylo = max(cy-r, 0), yhi = min(cy+r, G-1);
                const int xl  = max(cx-r, 0), xh  = min(cx+r, G-1);
                const int ny = yhi - ylo + 1;
                const int nrows = (zhi - zlo + 1) * ny;
                for (int rb = 0; rb < nrows; rb += 32) {
                    int rowid = rb + lane;
                    unsigned l2 = 0, h2 = 0;
                    if (rowid < nrows) {
                        int zi = rowid / ny;
                        int yi = rowid - zi * ny;
                        int rowb = ((zlo + zi)*G + (ylo + yi))*G;
                        l2 = off[rowb + xl];
                        h2 = off[rowb + xh + 1];
                    }
                    unsigned act = __ballot_sync(0xffffffffu, h2 > l2);
                    while (act) {
                        int src = __ffs(act) - 1;
                        act &= act - 1u;
                        unsigned rl = __shfl_sync(0xffffffffu, l2, src);
                        unsigned rh = __shfl_sync(0xffffffffu, h2, src);
                        for (unsigned k = rl + lane; k < rh; k += 32) {
                            float4 pt = pts[k];
                            float dx = pt.x - qx, dy = pt.y - qy, dz = pt.z - qz;
                            best = fminf(best, fmaf(dx, dx, fmaf(dy, dy, dz*dz)));
                        }
                    }
                }
                b = best;
                b = fminf(b, __shfl_xor_sync(0xffffffffu, b, 16));
                b = fminf(b, __shfl_xor_sync(0xffffffffu, b, 8));
                b = fminf(b, __shfl_xor_sync(0xffffffffu, b, 4));
                b = fminf(b, __shfl_xor_sync(0xffffffffu, b, 2));
                b = fminf(b, __shfl_xor_sync(0xffffffffu, b, 1));
                float bnd = (float)r * CS;
                if (bnd*bnd >= b) break;
            }
        }
        res = sqrtf(b);
    }

    if (lane == 0) swsum[wid] = res;
    __syncthreads();
    float v = 0.0f;
    if (wid == 0) {
        v = (lane < QWPB) ? swsum[lane] : 0.0f;
        v += __shfl_xor_sync(0xffffffffu, v, 4);
        v += __shfl_xor_sync(0xffffffffu, v, 2);
        v += __shfl_xor_sync(0xffffffffu, v, 1);
        if (lane == 0) {
            g_bsum[blockIdx.x] = v;
            __threadfence();
            unsigned t = atomicAdd(&g_ctr, 1u);
            swsum[0] = __uint_as_float(t);
        }
    }
    __syncthreads();
    if (__float_as_uint(swsum[0]) == QGRID - 1) {   // last block: total + reset
        __threadfence();
        float acc = 0.0f;
        for (int k = threadIdx.x; k < QGRID; k += QTPB) acc += g_bsum[k];
        #pragma unroll
        for (int o = 16; o; o >>= 1) acc += __shfl_down_sync(0xffffffffu, acc, o);
        if ((threadIdx.x & 31) == 0) swsum[wid] = acc;   // reuse smem (safe post-sync)
        __syncthreads();
        if (threadIdx.x == 0) {
            float t = 0.0f;
            #pragma unroll
            for (int k = 0; k < QWPB; k++) t += swsum[k];
            out[0] = t;
            g_ctr = 0;
        }
    }
}

extern "C" void kernel_launch(void* const* d_in, const int* in_sizes, int n_in,
                              void* d_out, int out_size) {
    const float* p1 = (const float*)d_in[0];
    const float* p2 = (const float*)d_in[1];
    int n1 = in_sizes[0] / 3;
    int n2 = in_sizes[1] / 3;
    float* out = (float*)d_out;

    int hb = (n1 + n2 + HTPB - 1) / HTPB;
    hist_kernel   <<<hb, HTPB>>>(p1, n1, p2, n2);
    scan_kernel   <<<2, STPB>>>();
    scatter_kernel<<<hb, HTPB>>>(p1, n1, p2, n2);
    query_kernel  <<<QGRID, QTPB>>>(p1, n1, p2, n2, out);   // launch #4 -> ncu
}